// round 16
// baseline (speedup 1.0000x reference)
#include <cuda_runtime.h>
#include <cuda_bf16.h>
#include <cstdint>
#include <math.h>

#define NN 50000
#define EE 400000
#define HC 128
#define EDIM 16
#define BN_EPS 1e-5f

// ---------------- scratch (device globals; no allocation allowed) ----------------
__device__ float g_Q[(size_t)NN * HC];
__device__ float g_K[(size_t)NN * HC];
__device__ float g_V[(size_t)NN * HC];
__device__ float g_S[(size_t)NN * HC];   // skip; overwritten with y = attn + skip

// bf16 hi/lo pre-split operands, k-quad-permuted
__device__ __nv_bfloat16 g_Ah[(size_t)NN * HC];
__device__ __nv_bfloat16 g_Al[(size_t)NN * HC];
__device__ __nv_bfloat16 g_Wth[8][HC * HC];   // W transposed: [n][k-permuted]; 0-3 L0, 4-7 L1
__device__ __nv_bfloat16 g_Wtl[8][HC * HC];

__device__ int g_deg[NN];
__device__ int g_cur[NN];
__device__ int g_off[NN + 1];
__device__ int g_srcs[EE];                  // src node per CSR position
__device__ float g_EAp[(size_t)EE * EDIM];  // EA permuted into CSR order
__device__ int g_bsum[256];
__device__ int g_boff[256];
__device__ float g_bnsum[HC];
__device__ float g_bnsq[HC];

// ---------------- bf16 hi/lo split helpers ----------------
__device__ __forceinline__ void bf16_split(float x, unsigned short& h, unsigned short& l) {
    __nv_bfloat16 hb = __float2bfloat16_rn(x);
    __nv_bfloat16 lb = __float2bfloat16_rn(x - __bfloat162float(hb));
    h = __bfloat16_as_ushort(hb);
    l = __bfloat16_as_ushort(lb);
}

// mega-split: A [N][128] (layer-0 input) + ALL 8 weight matrices, one launch.
// A thread i<nthrA: row=i>>5, quad qi=i&31. W thread j=i-nthrA: which=j>>12, n, qi.
__global__ void k_split(const float* __restrict__ A,
                        const float* __restrict__ w0, const float* __restrict__ w1,
                        const float* __restrict__ w2, const float* __restrict__ w3,
                        const float* __restrict__ w4, const float* __restrict__ w5,
                        const float* __restrict__ w6, const float* __restrict__ w7,
                        int nthrA)
{
    int i = blockIdx.x * blockDim.x + threadIdx.x;
    if (i < nthrA) {
        int row = i >> 5, qi = i & 31;
        int s = qi >> 2, t = qi & 3;
        const float* ap = A + (size_t)row * HC;
        float2 vlo = *(const float2*)&ap[16 * s + 2 * t];
        float2 vhi = *(const float2*)&ap[16 * s + 8 + 2 * t];
        unsigned short h0, l0, h1, l1, h2, l2, h3, l3;
        bf16_split(vlo.x, h0, l0);
        bf16_split(vlo.y, h1, l1);
        bf16_split(vhi.x, h2, l2);
        bf16_split(vhi.y, h3, l3);
        uint2 ph = make_uint2((unsigned)h0 | ((unsigned)h1 << 16),
                              (unsigned)h2 | ((unsigned)h3 << 16));
        uint2 pl = make_uint2((unsigned)l0 | ((unsigned)l1 << 16),
                              (unsigned)l2 | ((unsigned)l3 << 16));
        *(uint2*)&g_Ah[(size_t)row * HC + qi * 4] = ph;
        *(uint2*)&g_Al[(size_t)row * HC + qi * 4] = pl;
        return;
    }
    int j = i - nthrA;                 // 0 .. 8*4096-1
    if (j >= 8 * 4096) return;
    int which = j >> 12;
    int rem = j & 4095;
    int n = rem >> 5, qi = rem & 31;
    int s = qi >> 2, t = qi & 3;
    const float* w = which == 0 ? w0 : which == 1 ? w1 : which == 2 ? w2 : which == 3 ? w3
                   : which == 4 ? w4 : which == 5 ? w5 : which == 6 ? w6 : w7;
    float x0 = w[(size_t)(16 * s + 2 * t) * HC + n];
    float x1 = w[(size_t)(16 * s + 2 * t + 1) * HC + n];
    float x2 = w[(size_t)(16 * s + 8 + 2 * t) * HC + n];
    float x3 = w[(size_t)(16 * s + 9 + 2 * t) * HC + n];
    unsigned short h0, l0, h1, l1, h2, l2, h3, l3;
    bf16_split(x0, h0, l0);
    bf16_split(x1, h1, l1);
    bf16_split(x2, h2, l2);
    bf16_split(x3, h3, l3);
    uint2 ph = make_uint2((unsigned)h0 | ((unsigned)h1 << 16),
                          (unsigned)h2 | ((unsigned)h3 << 16));
    uint2 pl = make_uint2((unsigned)l0 | ((unsigned)l1 << 16),
                          (unsigned)l2 | ((unsigned)l3 << 16));
    *(uint2*)&g_Wth[which][(size_t)n * HC + qi * 4] = ph;
    *(uint2*)&g_Wtl[which][(size_t)n * HC + qi * 4] = pl;
}

// ---------------- CSR build ----------------
__global__ void k_zero_csr() {
    int i = blockIdx.x * blockDim.x + threadIdx.x;
    if (i < NN) { g_deg[i] = 0; g_cur[i] = 0; }
}

__global__ void k_hist(const int* __restrict__ dst) {
    int e = blockIdx.x * blockDim.x + threadIdx.x;
    if (e < EE) atomicAdd(&g_deg[dst[e]], 1);
}

__global__ void k_scan1() {
    __shared__ int sh[256];
    int tid = threadIdx.x;
    int i = blockIdx.x * 256 + tid;
    int v = (i < NN) ? g_deg[i] : 0;
    sh[tid] = v;
    __syncthreads();
    for (int o = 1; o < 256; o <<= 1) {
        int t = (tid >= o) ? sh[tid - o] : 0;
        __syncthreads();
        sh[tid] += t;
        __syncthreads();
    }
    if (i < NN) g_off[i] = sh[tid] - v;
    if (tid == 255) g_bsum[blockIdx.x] = sh[255];
}

__global__ void k_scan2(int nb) {
    __shared__ int sh[256];
    int tid = threadIdx.x;
    int v = (tid < nb) ? g_bsum[tid] : 0;
    sh[tid] = v;
    __syncthreads();
    for (int o = 1; o < 256; o <<= 1) {
        int t = (tid >= o) ? sh[tid - o] : 0;
        __syncthreads();
        sh[tid] += t;
        __syncthreads();
    }
    g_boff[tid] = sh[tid] - v;
}

__global__ void k_scan3() {
    int i = blockIdx.x * 256 + threadIdx.x;
    if (i < NN) g_off[i] += g_boff[blockIdx.x];
    if (i == 0) g_off[NN] = EE;
}

// fused fill + EA permute + src materialize (no eids indirection)
__global__ void k_fillperm(const int* __restrict__ dst, const int* __restrict__ src,
                           const float* __restrict__ EA) {
    int e = blockIdx.x * blockDim.x + threadIdx.x;
    if (e >= EE) return;
    int d = dst[e];
    int pos = g_off[d] + atomicAdd(&g_cur[d], 1);
    g_srcs[pos] = src[e];
    const float4* s4 = (const float4*)&EA[(size_t)e * EDIM];
    float4* d4 = (float4*)&g_EAp[(size_t)pos * EDIM];
    d4[0] = s4[0]; d4[1] = s4[1]; d4[2] = s4[2]; d4[3] = s4[3];
}

// ---------------- fused bf16x2 tensor-core GEMM, 2-stage pipelined ----------------
// BK=32 x 4 chunks, double-buffered cp.async. 8 warps, warp tile 64x32, 2 CTA/SM.
#define SR32 40                      // smem row stride in bf16 (32 data + 8 pad = 80B)
#define PLANE32 (128 * SR32)         // 5120 bf16 per plane
#define STAGE32 (4 * PLANE32)        // Ah,Al,Bh,Bl
#define G4_SMEM (2 * STAGE32 * 2)    // 81920 bytes

__device__ __forceinline__ void cpa16(unsigned int dst, const void* src, int bytes) {
    asm volatile("cp.async.ca.shared.global [%0], [%1], 16, %2;\n"
                 :: "r"(dst), "l"(src), "r"(bytes));
}

__device__ __forceinline__ void mma16(float* d, unsigned a0, unsigned a1, unsigned a2,
                                      unsigned a3, unsigned b0, unsigned b1) {
    asm volatile(
        "mma.sync.aligned.m16n8k16.row.col.f32.bf16.bf16.f32 "
        "{%0,%1,%2,%3}, {%4,%5,%6,%7}, {%8,%9}, {%0,%1,%2,%3};\n"
        : "+f"(d[0]), "+f"(d[1]), "+f"(d[2]), "+f"(d[3])
        : "r"(a0), "r"(a1), "r"(a2), "r"(a3), "r"(b0), "r"(b1));
}

__global__ void __launch_bounds__(256, 2) k_gemm4(
    const float* __restrict__ b0p, const float* __restrict__ b1p,
    const float* __restrict__ b2p, const float* __restrict__ b3p,
    float* __restrict__ o0p, float* __restrict__ o1p,
    float* __restrict__ o2p, float* __restrict__ o3p, int M, int whichBase)
{
    extern __shared__ __nv_bfloat16 sm[];
    unsigned int sm_u = (unsigned int)__cvta_generic_to_shared(sm);

    int tid = threadIdx.x;
    int wid = tid >> 5, lane = tid & 31;
    int g = lane >> 2, tig = lane & 3;
    int m0 = (wid & 1) * 64;
    int n0 = (wid >> 1) * 32;
    int brow = blockIdx.x * 128;
    int which = whichBase + blockIdx.y;

    const __nv_bfloat16* Wh = &g_Wth[which][0];
    const __nv_bfloat16* Wl = &g_Wtl[which][0];
    const float* bias = blockIdx.y == 0 ? b0p : blockIdx.y == 1 ? b1p
                      : blockIdx.y == 2 ? b2p : b3p;
    float* C = blockIdx.y == 0 ? o0p : blockIdx.y == 1 ? o1p
             : blockIdx.y == 2 ? o2p : o3p;

    float acc[4][4][4];
#pragma unroll
    for (int i = 0; i < 4; i++)
#pragma unroll
        for (int j = 0; j < 4; j++)
#pragma unroll
            for (int r = 0; r < 4; r++) acc[i][j][r] = 0.f;

    // loader lambda-ish via macro: stage s, chunk k0
    // items: 512 per plane (128 rows x 4 x 16B); thread does 2 per plane
#define LOAD_CHUNK(S, K0)                                                           \
    {                                                                               \
        unsigned int base = sm_u + (S) * STAGE32 * 2;                               \
        _Pragma("unroll")                                                           \
        for (int j = 0; j < 2; j++) {                                               \
            int idx = tid + j * 256;                                                \
            int row = idx >> 2;                                                     \
            int c = idx & 3;                                                        \
            int grow = brow + row;                                                  \
            int nb = (grow < M) ? 16 : 0;                                           \
            unsigned off = (unsigned)(row * SR32 + c * 8) * 2;                      \
            cpa16(base + off, &g_Ah[(size_t)grow * HC + (K0) + c * 8], nb);         \
            cpa16(base + PLANE32 * 2 + off,                                         \
                  &g_Al[(size_t)grow * HC + (K0) + c * 8], nb);                     \
            cpa16(base + 2 * PLANE32 * 2 + off,                                     \
                  &Wh[(size_t)row * HC + (K0) + c * 8], 16);                        \
            cpa16(base + 3 * PLANE32 * 2 + off,                                     \
                  &Wl[(size_t)row * HC + (K0) + c * 8], 16);                        \
        }                                                                           \
        asm volatile("cp.async.commit_group;\n");                                   \
    }

    LOAD_CHUNK(0, 0);

    for (int ch = 0; ch < 4; ch++) {
        int cur = ch & 1;
        if (ch < 3) LOAD_CHUNK(cur ^ 1, (ch + 1) * 32);
        if (ch < 3) asm volatile("cp.async.wait_group 1;\n");
        else        asm volatile("cp.async.wait_group 0;\n");
        __syncthreads();

        const __nv_bfloat16* Ahs = sm + cur * STAGE32;
        const __nv_bfloat16* Als = Ahs + PLANE32;
        const __nv_bfloat16* Bhs = Ahs + 2 * PLANE32;
        const __nv_bfloat16* Bls = Ahs + 3 * PLANE32;

#pragma unroll
        for (int ks = 0; ks < 2; ks++) {
            int kq = ks * 16 + tig * 4;
            unsigned bh[4][2], bl[4][2];
#pragma unroll
            for (int nf = 0; nf < 4; nf++) {
                int nrow = n0 + nf * 8 + g;
                uint2 vh = *(const uint2*)&Bhs[nrow * SR32 + kq];
                uint2 vl = *(const uint2*)&Bls[nrow * SR32 + kq];
                bh[nf][0] = vh.x; bh[nf][1] = vh.y;
                bl[nf][0] = vl.x; bl[nf][1] = vl.y;
            }
#pragma unroll
            for (int mf = 0; mf < 4; mf++) {
                int ar = (m0 + mf * 16 + g) * SR32 + kq;
                uint2 h0 = *(const uint2*)&Ahs[ar];
                uint2 h1 = *(const uint2*)&Ahs[ar + 8 * SR32];
                uint2 l0 = *(const uint2*)&Als[ar];
                uint2 l1 = *(const uint2*)&Als[ar + 8 * SR32];
#pragma unroll
                for (int nf = 0; nf < 4; nf++) {
                    float* d = acc[mf][nf];
                    mma16(d, h0.x, h1.x, h0.y, h1.y, bh[nf][0], bh[nf][1]);
                    mma16(d, h0.x, h1.x, h0.y, h1.y, bl[nf][0], bl[nf][1]);
                    mma16(d, l0.x, l1.x, l0.y, l1.y, bh[nf][0], bh[nf][1]);
                }
            }
        }
        __syncthreads();   // compute done before next load overwrites this stage
    }

#pragma unroll
    for (int nf = 0; nf < 4; nf++) {
        int col = n0 + nf * 8 + tig * 2;
        float b0v = bias[col], b1v = bias[col + 1];
#pragma unroll
        for (int mf = 0; mf < 4; mf++) {
            int r0 = brow + m0 + mf * 16 + g;
            float* d = acc[mf][nf];
            if (r0 < M)
                *(float2*)&C[(size_t)r0 * 128 + col] = make_float2(d[0] + b0v, d[1] + b1v);
            if (r0 + 8 < M)
                *(float2*)&C[(size_t)(r0 + 8) * 128 + col] = make_float2(d[2] + b0v, d[3] + b1v);
        }
    }
}

// ---------------- edge attention v5 (+ fused bn-accumulator zeroing) ----------------
__global__ void __launch_bounds__(256) k_edge(const float* __restrict__ EW)
{
    if (blockIdx.x == 0 && threadIdx.x < HC) {
        g_bnsum[threadIdx.x] = 0.f;
        g_bnsq[threadIdx.x] = 0.f;
    }

    __shared__ __align__(16) float4 ews[16 * 32];
    for (int i = threadIdx.x; i < 16 * 32; i += 256)
        ews[i] = ((const float4*)EW)[i];
    __syncthreads();

    int warp = (blockIdx.x * 256 + threadIdx.x) >> 5;
    int lane = threadIdx.x & 31;
    if (warp >= NN) return;
    int node = warp;
    int sub = lane & 7;
    int beg = g_off[node], end = g_off[node + 1];

    float4 qv = *(const float4*)&g_Q[(size_t)node * HC + lane * 4];

    float p0 = 0.f, p1 = 0.f;
#pragma unroll
    for (int d = 0; d < EDIM; d++) {
        float4 wc = ews[d * 32 + lane];
        float part = qv.x * wc.x + qv.y * wc.y + qv.z * wc.z + qv.w * wc.w;
        part += __shfl_xor_sync(0xffffffffu, part, 1);
        part += __shfl_xor_sync(0xffffffffu, part, 2);
        part += __shfl_xor_sync(0xffffffffu, part, 4);
        if (d == 2 * sub) p0 = part;
        if (d == 2 * sub + 1) p1 = part;
    }

    float m = -1e30f, s = 0.f;
    float ax = 0.f, ay = 0.f, az = 0.f, aw = 0.f;
    float g0 = 0.f, g1 = 0.f;

    int p = beg;
    for (; p + 4 <= end; p += 4) {
        int sn[4];
#pragma unroll
        for (int j = 0; j < 4; j++) sn[j] = g_srcs[p + j];
        float2 ea[4];
#pragma unroll
        for (int j = 0; j < 4; j++)
            ea[j] = *(const float2*)&g_EAp[(size_t)(p + j) * EDIM + 2 * sub];
        float4 kv[4], vv[4];
#pragma unroll
        for (int j = 0; j < 4; j++)
            kv[j] = *(const float4*)&g_K[(size_t)sn[j] * HC + lane * 4];
#pragma unroll
        for (int j = 0; j < 4; j++)
            vv[j] = *(const float4*)&g_V[(size_t)sn[j] * HC + lane * 4];

        float a[4];
#pragma unroll
        for (int j = 0; j < 4; j++) {
            float part = qv.x * kv[j].x + qv.y * kv[j].y + qv.z * kv[j].z + qv.w * kv[j].w
                       + ea[j].x * p0 + ea[j].y * p1;
            part += __shfl_xor_sync(0xffffffffu, part, 1);
            part += __shfl_xor_sync(0xffffffffu, part, 2);
            part += __shfl_xor_sync(0xffffffffu, part, 4);
            a[j] = part * 0.17677669529663687f;
        }
        float nm = fmaxf(m, fmaxf(fmaxf(a[0], a[1]), fmaxf(a[2], a[3])));
        float sc = __expf(m - nm);
        float pe0 = __expf(a[0] - nm), pe1 = __expf(a[1] - nm);
        float pe2 = __expf(a[2] - nm), pe3 = __expf(a[3] - nm);
        s = s * sc + ((pe0 + pe1) + (pe2 + pe3));
        ax = ax * sc + ((pe0 * vv[0].x + pe1 * vv[1].x) + (pe2 * vv[2].x + pe3 * vv[3].x));
        ay = ay * sc + ((pe0 * vv[0].y + pe1 * vv[1].y) + (pe2 * vv[2].y + pe3 * vv[3].y));
        az = az * sc + ((pe0 * vv[0].z + pe1 * vv[1].z) + (pe2 * vv[2].z + pe3 * vv[3].z));
        aw = aw * sc + ((pe0 * vv[0].w + pe1 * vv[1].w) + (pe2 * vv[2].w + pe3 * vv[3].w));
        g0 = g0 * sc + ((pe0 * ea[0].x + pe1 * ea[1].x) + (pe2 * ea[2].x + pe3 * ea[3].x));
        g1 = g1 * sc + ((pe0 * ea[0].y + pe1 * ea[1].y) + (pe2 * ea[2].y + pe3 * ea[3].y));
        m = nm;
    }
    for (; p < end; p++) {
        int sn = g_srcs[p];
        float2 ea2 = *(const float2*)&g_EAp[(size_t)p * EDIM + 2 * sub];
        float4 kv = *(const float4*)&g_K[(size_t)sn * HC + lane * 4];
        float part = qv.x * kv.x + qv.y * kv.y + qv.z * kv.z + qv.w * kv.w
                   + ea2.x * p0 + ea2.y * p1;
        part += __shfl_xor_sync(0xffffffffu, part, 1);
        part += __shfl_xor_sync(0xffffffffu, part, 2);
        part += __shfl_xor_sync(0xffffffffu, part, 4);
        float a = part * 0.17677669529663687f;
        float nm = fmaxf(m, a);
        float sc = __expf(m - nm);
        float pe = __expf(a - nm);
        s = s * sc + pe;
        float4 vv = *(const float4*)&g_V[(size_t)sn * HC + lane * 4];
        ax = ax * sc + pe * vv.x;
        ay = ay * sc + pe * vv.y;
        az = az * sc + pe * vv.z;
        aw = aw * sc + pe * vv.w;
        g0 = g0 * sc + pe * ea2.x;
        g1 = g1 * sc + pe * ea2.y;
        m = nm;
    }

    float ex = 0.f, ey = 0.f, ez = 0.f, ew_ = 0.f;
    int base = lane & ~7;
#pragma unroll
    for (int j = 0; j < 8; j++) {
        float gg0 = __shfl_sync(0xffffffffu, g0, base + j);
        float gg1 = __shfl_sync(0xffffffffu, g1, base + j);
        float4 w0 = ews[(2 * j) * 32 + lane];
        float4 w1 = ews[(2 * j + 1) * 32 + lane];
        ex += gg0 * w0.x + gg1 * w1.x;
        ey += gg0 * w0.y + gg1 * w1.y;
        ez += gg0 * w0.z + gg1 * w1.z;
        ew_ += gg0 * w0.w + gg1 * w1.w;
    }

    float inv = (end > beg) ? (1.f / s) : 0.f;
    size_t o = (size_t)node * HC + lane * 4;
    float4 sv = *(const float4*)&g_S[o];
    float4 y = make_float4((ax + ex) * inv + sv.x, (ay + ey) * inv + sv.y,
                           (az + ez) * inv + sv.z, (aw + ew_) * inv + sv.w);
    *(float4*)&g_S[o] = y;
}

// ---------------- batchnorm + relu ----------------
__global__ void k_bn_reduce() {
    int c = threadIdx.x;
    float sum = 0.f, sq = 0.f;
    for (int n = blockIdx.x; n < NN; n += gridDim.x) {
        float v = g_S[(size_t)n * HC + c];
        sum += v; sq += v * v;
    }
    atomicAdd(&g_bnsum[c], sum);
    atomicAdd(&g_bnsq[c], sq);
}

__global__ void k_bn_apply(const float* __restrict__ gamma,
                           const float* __restrict__ beta,
                           float* __restrict__ out, int do_split)
{
    int i = blockIdx.x * blockDim.x + threadIdx.x;
    if (i >= NN * HC) return;
    int c = i & 127;
    int n = i >> 7;
    float mean = g_bnsum[c] * (1.f / NN);
    float var = fmaf(-mean, mean, g_bnsq[c] * (1.f / NN));
    float v = (g_S[i] - mean) * rsqrtf(var + BN_EPS) * gamma[c] + beta[c];
    float r = fmaxf(v, 0.f);
    out[i] = r;
    if (do_split) {
        int s = c >> 4, r15 = c & 15;
        int t, pq;
        if (r15 < 8) { t = r15 >> 1; pq = r15 & 1; }
        else { t = (r15 - 8) >> 1; pq = 2 + (r15 & 1); }
        int pos = s * 16 + t * 4 + pq;
        unsigned short h, l;
        bf16_split(r, h, l);
        g_Ah[(size_t)n * HC + pos] = __ushort_as_bfloat16(h);
        g_Al[(size_t)n * HC + pos] = __ushort_as_bfloat16(l);
    }
}

// ---------------- driver ----------------
extern "C" void kernel_launch(void* const* d_in, const int* in_sizes, int n_in,
                              void* d_out, int out_size)
{
    const float* x  = (const float*)d_in[0];
    const int*   ei = (const int*)d_in[1];
    const float* ea = (const float*)d_in[2];
    const int* src = ei;
    const int* dst = ei + EE;

    float* out = (float*)d_out;
    float* x1 = out;
    float* x2 = out + (size_t)NN * HC;

    float *Q, *K, *V, *S;
    cudaGetSymbolAddress((void**)&Q, g_Q);
    cudaGetSymbolAddress((void**)&K, g_K);
    cudaGetSymbolAddress((void**)&V, g_V);
    cudaGetSymbolAddress((void**)&S, g_S);

    cudaFuncSetAttribute(k_gemm4, cudaFuncAttributeMaxDynamicSharedMemorySize, G4_SMEM);

    const int NB1 = (NN + 255) / 256;
    const dim3 gg4((NN + 127) / 128, 4);
    const int nthrA = NN * 32;
    const int nthrSplit = nthrA + 8 * 4096;

    for (int L = 0; L < 2; L++) {
        int b = 3 + L * 11;
        const float* qb = (const float*)d_in[b + 1];
        const float* kb = (const float*)d_in[b + 3];
        const float* vb = (const float*)d_in[b + 5];
        const float* sb = (const float*)d_in[b + 8];
        const float* bg = (const float*)d_in[b + 9];
        const float* bb = (const float*)d_in[b + 10];
        const float* ew = (const float*)d_in[b + 6];

        if (L == 0) {
            k_split<<<(nthrSplit + 255) / 256, 256>>>(
                x,
                (const float*)d_in[3], (const float*)d_in[5],
                (const float*)d_in[7], (const float*)d_in[10],
                (const float*)d_in[14], (const float*)d_in[16],
                (const float*)d_in[18], (const float*)d_in[21], nthrA);           // 0
            k_zero_csr<<<NB1, 256>>>();                                            // 1
            k_hist<<<(EE + 255) / 256, 256>>>(dst);                                // 2
            k_gemm4<<<gg4, 256, G4_SMEM>>>(qb, kb, vb, sb, Q, K, V, S, NN, 0);     // 3 (profiled)
            k_scan1<<<NB1, 256>>>();
            k_scan2<<<1, 256>>>(NB1);
            k_scan3<<<NB1, 256>>>();
            k_fillperm<<<(EE + 255) / 256, 256>>>(dst, src, ea);
        } else {
            k_gemm4<<<gg4, 256, G4_SMEM>>>(qb, kb, vb, sb, Q, K, V, S, NN, 4);
        }

        k_edge<<<(NN * 32 + 255) / 256, 256>>>(ew);

        k_bn_reduce<<<512, 128>>>();
        k_bn_apply<<<(NN * HC + 255) / 256, 256>>>(bg, bb, (L == 0) ? x1 : x2,
                                                   (L == 0) ? 1 : 0);
    }
}

// round 17
// speedup vs baseline: 1.0506x; 1.0506x over previous
#include <cuda_runtime.h>
#include <cuda_bf16.h>
#include <cstdint>
#include <math.h>

#define NN 50000
#define EE 400000
#define HC 128
#define EDIM 16
#define BN_EPS 1e-5f

// ---------------- scratch (device globals; no allocation allowed) ----------------
__device__ float g_Q[(size_t)NN * HC];
__device__ float g_K[(size_t)NN * HC];
__device__ float g_V[(size_t)NN * HC];
__device__ float g_S[(size_t)NN * HC];   // skip; overwritten with y = attn + skip

// bf16 hi/lo pre-split operands, k-quad-permuted
__device__ __nv_bfloat16 g_Ah[(size_t)NN * HC];
__device__ __nv_bfloat16 g_Al[(size_t)NN * HC];
__device__ __nv_bfloat16 g_Wth[8][HC * HC];   // W transposed: [n][k-permuted]; 0-3 L0, 4-7 L1
__device__ __nv_bfloat16 g_Wtl[8][HC * HC];

__device__ int g_deg[NN];
__device__ int g_cur[NN];
__device__ int g_off[NN + 1];
__device__ int g_srcs[EE];                  // src node per CSR position
__device__ float g_EAp[(size_t)EE * EDIM];  // EA permuted into CSR order
__device__ int g_bsum[256];
__device__ int g_boff[256];
__device__ float g_bnsum[HC];
__device__ float g_bnsq[HC];

// ---------------- bf16 hi/lo split helpers ----------------
__device__ __forceinline__ void bf16_split(float x, unsigned short& h, unsigned short& l) {
    __nv_bfloat16 hb = __float2bfloat16_rn(x);
    __nv_bfloat16 lb = __float2bfloat16_rn(x - __bfloat162float(hb));
    h = __bfloat16_as_ushort(hb);
    l = __bfloat16_as_ushort(lb);
}

// mega-split: A [N][128] (layer-0 input) + ALL 8 weight matrices, one launch.
__global__ void k_split(const float* __restrict__ A,
                        const float* __restrict__ w0, const float* __restrict__ w1,
                        const float* __restrict__ w2, const float* __restrict__ w3,
                        const float* __restrict__ w4, const float* __restrict__ w5,
                        const float* __restrict__ w6, const float* __restrict__ w7,
                        int nthrA)
{
    int i = blockIdx.x * blockDim.x + threadIdx.x;
    if (i < nthrA) {
        int row = i >> 5, qi = i & 31;
        int s = qi >> 2, t = qi & 3;
        const float* ap = A + (size_t)row * HC;
        float2 vlo = *(const float2*)&ap[16 * s + 2 * t];
        float2 vhi = *(const float2*)&ap[16 * s + 8 + 2 * t];
        unsigned short h0, l0, h1, l1, h2, l2, h3, l3;
        bf16_split(vlo.x, h0, l0);
        bf16_split(vlo.y, h1, l1);
        bf16_split(vhi.x, h2, l2);
        bf16_split(vhi.y, h3, l3);
        uint2 ph = make_uint2((unsigned)h0 | ((unsigned)h1 << 16),
                              (unsigned)h2 | ((unsigned)h3 << 16));
        uint2 pl = make_uint2((unsigned)l0 | ((unsigned)l1 << 16),
                              (unsigned)l2 | ((unsigned)l3 << 16));
        *(uint2*)&g_Ah[(size_t)row * HC + qi * 4] = ph;
        *(uint2*)&g_Al[(size_t)row * HC + qi * 4] = pl;
        return;
    }
    int j = i - nthrA;                 // 0 .. 8*4096-1
    if (j >= 8 * 4096) return;
    int which = j >> 12;
    int rem = j & 4095;
    int n = rem >> 5, qi = rem & 31;
    int s = qi >> 2, t = qi & 3;
    const float* w = which == 0 ? w0 : which == 1 ? w1 : which == 2 ? w2 : which == 3 ? w3
                   : which == 4 ? w4 : which == 5 ? w5 : which == 6 ? w6 : w7;
    float x0 = w[(size_t)(16 * s + 2 * t) * HC + n];
    float x1 = w[(size_t)(16 * s + 2 * t + 1) * HC + n];
    float x2 = w[(size_t)(16 * s + 8 + 2 * t) * HC + n];
    float x3 = w[(size_t)(16 * s + 9 + 2 * t) * HC + n];
    unsigned short h0, l0, h1, l1, h2, l2, h3, l3;
    bf16_split(x0, h0, l0);
    bf16_split(x1, h1, l1);
    bf16_split(x2, h2, l2);
    bf16_split(x3, h3, l3);
    uint2 ph = make_uint2((unsigned)h0 | ((unsigned)h1 << 16),
                          (unsigned)h2 | ((unsigned)h3 << 16));
    uint2 pl = make_uint2((unsigned)l0 | ((unsigned)l1 << 16),
                          (unsigned)l2 | ((unsigned)l3 << 16));
    *(uint2*)&g_Wth[which][(size_t)n * HC + qi * 4] = ph;
    *(uint2*)&g_Wtl[which][(size_t)n * HC + qi * 4] = pl;
}

// ---------------- CSR build ----------------
__global__ void k_zero_csr() {
    int i = blockIdx.x * blockDim.x + threadIdx.x;
    if (i < NN) { g_deg[i] = 0; g_cur[i] = 0; }
}

__global__ void k_hist(const int* __restrict__ dst) {
    int e = blockIdx.x * blockDim.x + threadIdx.x;
    if (e < EE) atomicAdd(&g_deg[dst[e]], 1);
}

__global__ void k_scan1() {
    __shared__ int sh[256];
    int tid = threadIdx.x;
    int i = blockIdx.x * 256 + tid;
    int v = (i < NN) ? g_deg[i] : 0;
    sh[tid] = v;
    __syncthreads();
    for (int o = 1; o < 256; o <<= 1) {
        int t = (tid >= o) ? sh[tid - o] : 0;
        __syncthreads();
        sh[tid] += t;
        __syncthreads();
    }
    if (i < NN) g_off[i] = sh[tid] - v;
    if (tid == 255) g_bsum[blockIdx.x] = sh[255];
}

__global__ void k_scan2(int nb) {
    __shared__ int sh[256];
    int tid = threadIdx.x;
    int v = (tid < nb) ? g_bsum[tid] : 0;
    sh[tid] = v;
    __syncthreads();
    for (int o = 1; o < 256; o <<= 1) {
        int t = (tid >= o) ? sh[tid - o] : 0;
        __syncthreads();
        sh[tid] += t;
        __syncthreads();
    }
    g_boff[tid] = sh[tid] - v;
}

__global__ void k_scan3() {
    int i = blockIdx.x * 256 + threadIdx.x;
    if (i < NN) g_off[i] += g_boff[blockIdx.x];
    if (i == 0) g_off[NN] = EE;
}

// fused fill + EA permute + src materialize (no eids indirection)
__global__ void k_fillperm(const int* __restrict__ dst, const int* __restrict__ src,
                           const float* __restrict__ EA) {
    int e = blockIdx.x * blockDim.x + threadIdx.x;
    if (e >= EE) return;
    int d = dst[e];
    int pos = g_off[d] + atomicAdd(&g_cur[d], 1);
    g_srcs[pos] = src[e];
    const float4* s4 = (const float4*)&EA[(size_t)e * EDIM];
    float4* d4 = (float4*)&g_EAp[(size_t)pos * EDIM];
    d4[0] = s4[0]; d4[1] = s4[1]; d4[2] = s4[2]; d4[3] = s4[3];
}

// ---------------- fused bf16x2 tensor-core GEMM (Q,K,V,S in one launch) ----------------
// C = A@W + bias via (ah+al)(bh+bl) ~= ah.bh + ah.bl + al.bh, mma.m16n8k16.bf16
// BM=128, BN=128, BK=64 x 2 chunks. 8 warps, warp tile 64x32. 2 CTAs/SM.
// SROW=80 bf16 (160B rows) -- measured conflict-free for the LDS.64 fragment pattern.
#define SROW 80
#define PLANE (128 * SROW)
#define G4_SMEM (4 * PLANE * 2)   // 81920 bytes

__device__ __forceinline__ void cpa16(unsigned int dst, const void* src, int bytes) {
    asm volatile("cp.async.ca.shared.global [%0], [%1], 16, %2;\n"
                 :: "r"(dst), "l"(src), "r"(bytes));
}

__device__ __forceinline__ void mma16(float* d, unsigned a0, unsigned a1, unsigned a2,
                                      unsigned a3, unsigned b0, unsigned b1) {
    asm volatile(
        "mma.sync.aligned.m16n8k16.row.col.f32.bf16.bf16.f32 "
        "{%0,%1,%2,%3}, {%4,%5,%6,%7}, {%8,%9}, {%0,%1,%2,%3};\n"
        : "+f"(d[0]), "+f"(d[1]), "+f"(d[2]), "+f"(d[3])
        : "r"(a0), "r"(a1), "r"(a2), "r"(a3), "r"(b0), "r"(b1));
}

__global__ void __launch_bounds__(256, 2) k_gemm4(
    const float* __restrict__ b0p, const float* __restrict__ b1p,
    const float* __restrict__ b2p, const float* __restrict__ b3p,
    float* __restrict__ o0p, float* __restrict__ o1p,
    float* __restrict__ o2p, float* __restrict__ o3p, int M, int whichBase)
{
    extern __shared__ __nv_bfloat16 sm[];
    __nv_bfloat16* Ah = sm;
    __nv_bfloat16* Al = sm + PLANE;
    __nv_bfloat16* Bh = sm + 2 * PLANE;
    __nv_bfloat16* Bl = sm + 3 * PLANE;
    unsigned int Ah_u = (unsigned int)__cvta_generic_to_shared(Ah);
    unsigned int Al_u = (unsigned int)__cvta_generic_to_shared(Al);
    unsigned int Bh_u = (unsigned int)__cvta_generic_to_shared(Bh);
    unsigned int Bl_u = (unsigned int)__cvta_generic_to_shared(Bl);

    int tid = threadIdx.x;
    int wid = tid >> 5, lane = tid & 31;
    int g = lane >> 2, tig = lane & 3;
    int m0 = (wid & 1) * 64;
    int n0 = (wid >> 1) * 32;
    int brow = blockIdx.x * 128;
    int which = whichBase + blockIdx.y;

    const __nv_bfloat16* Wh = &g_Wth[which][0];
    const __nv_bfloat16* Wl = &g_Wtl[which][0];
    const float* bias = blockIdx.y == 0 ? b0p : blockIdx.y == 1 ? b1p
                      : blockIdx.y == 2 ? b2p : b3p;
    float* C = blockIdx.y == 0 ? o0p : blockIdx.y == 1 ? o1p
             : blockIdx.y == 2 ? o2p : o3p;

    float acc[4][4][4];
#pragma unroll
    for (int i = 0; i < 4; i++)
#pragma unroll
        for (int j = 0; j < 4; j++)
#pragma unroll
            for (int r = 0; r < 4; r++) acc[i][j][r] = 0.f;

    for (int k0 = 0; k0 < 128; k0 += 64) {
#pragma unroll
        for (int j = 0; j < 4; j++) {
            int idx = tid + j * 256;
            int row = idx >> 3;
            int c = idx & 7;
            int grow = brow + row;
            int nb = (grow < M) ? 16 : 0;
            unsigned off = (unsigned)(row * SROW + c * 8) * 2;
            cpa16(Ah_u + off, &g_Ah[(size_t)grow * HC + k0 + c * 8], nb);
            cpa16(Al_u + off, &g_Al[(size_t)grow * HC + k0 + c * 8], nb);
        }
#pragma unroll
        for (int j = 0; j < 4; j++) {
            int idx = tid + j * 256;
            int row = idx >> 3;
            int c = idx & 7;
            unsigned off = (unsigned)(row * SROW + c * 8) * 2;
            cpa16(Bh_u + off, &Wh[(size_t)row * HC + k0 + c * 8], 16);
            cpa16(Bl_u + off, &Wl[(size_t)row * HC + k0 + c * 8], 16);
        }
        asm volatile("cp.async.commit_group;\n");
        asm volatile("cp.async.wait_group 0;\n");
        __syncthreads();

#pragma unroll
        for (int ks = 0; ks < 4; ks++) {
            int kq = ks * 16 + tig * 4;
            unsigned bh[4][2], bl[4][2];
#pragma unroll
            for (int nf = 0; nf < 4; nf++) {
                int nrow = n0 + nf * 8 + g;
                uint2 vh = *(const uint2*)&Bh[nrow * SROW + kq];
                uint2 vl = *(const uint2*)&Bl[nrow * SROW + kq];
                bh[nf][0] = vh.x; bh[nf][1] = vh.y;
                bl[nf][0] = vl.x; bl[nf][1] = vl.y;
            }
#pragma unroll
            for (int mf = 0; mf < 4; mf++) {
                int ar = (m0 + mf * 16 + g) * SROW + kq;
                uint2 h0 = *(const uint2*)&Ah[ar];
                uint2 h1 = *(const uint2*)&Ah[ar + 8 * SROW];
                uint2 l0 = *(const uint2*)&Al[ar];
                uint2 l1 = *(const uint2*)&Al[ar + 8 * SROW];
#pragma unroll
                for (int nf = 0; nf < 4; nf++) {
                    float* d = acc[mf][nf];
                    mma16(d, h0.x, h1.x, h0.y, h1.y, bh[nf][0], bh[nf][1]);
                    mma16(d, h0.x, h1.x, h0.y, h1.y, bl[nf][0], bl[nf][1]);
                    mma16(d, l0.x, l1.x, l0.y, l1.y, bh[nf][0], bh[nf][1]);
                }
            }
        }
        __syncthreads();
    }

#pragma unroll
    for (int nf = 0; nf < 4; nf++) {
        int col = n0 + nf * 8 + tig * 2;
        float b0v = bias[col], b1v = bias[col + 1];
#pragma unroll
        for (int mf = 0; mf < 4; mf++) {
            int r0 = brow + m0 + mf * 16 + g;
            float* d = acc[mf][nf];
            if (r0 < M)
                *(float2*)&C[(size_t)r0 * 128 + col] = make_float2(d[0] + b0v, d[1] + b1v);
            if (r0 + 8 < M)
                *(float2*)&C[(size_t)(r0 + 8) * 128 + col] = make_float2(d[2] + b0v, d[3] + b1v);
        }
    }
}

// ---------------- edge attention v5 (+ fused bn-accumulator zeroing) ----------------
__global__ void __launch_bounds__(256) k_edge(const float* __restrict__ EW)
{
    if (blockIdx.x == 0 && threadIdx.x < HC) {
        g_bnsum[threadIdx.x] = 0.f;
        g_bnsq[threadIdx.x] = 0.f;
    }

    __shared__ __align__(16) float4 ews[16 * 32];
    for (int i = threadIdx.x; i < 16 * 32; i += 256)
        ews[i] = ((const float4*)EW)[i];
    __syncthreads();

    int warp = (blockIdx.x * 256 + threadIdx.x) >> 5;
    int lane = threadIdx.x & 31;
    if (warp >= NN) return;
    int node = warp;
    int sub = lane & 7;
    int beg = g_off[node], end = g_off[node + 1];

    float4 qv = *(const float4*)&g_Q[(size_t)node * HC + lane * 4];

    float p0 = 0.f, p1 = 0.f;
#pragma unroll
    for (int d = 0; d < EDIM; d++) {
        float4 wc = ews[d * 32 + lane];
        float part = qv.x * wc.x + qv.y * wc.y + qv.z * wc.z + qv.w * wc.w;
        part += __shfl_xor_sync(0xffffffffu, part, 1);
        part += __shfl_xor_sync(0xffffffffu, part, 2);
        part += __shfl_xor_sync(0xffffffffu, part, 4);
        if (d == 2 * sub) p0 = part;
        if (d == 2 * sub + 1) p1 = part;
    }

    float m = -1e30f, s = 0.f;
    float ax = 0.f, ay = 0.f, az = 0.f, aw = 0.f;
    float g0 = 0.f, g1 = 0.f;

    int p = beg;
    for (; p + 4 <= end; p += 4) {
        int sn[4];
#pragma unroll
        for (int j = 0; j < 4; j++) sn[j] = g_srcs[p + j];
        float2 ea[4];
#pragma unroll
        for (int j = 0; j < 4; j++)
            ea[j] = *(const float2*)&g_EAp[(size_t)(p + j) * EDIM + 2 * sub];
        float4 kv[4], vv[4];
#pragma unroll
        for (int j = 0; j < 4; j++)
            kv[j] = *(const float4*)&g_K[(size_t)sn[j] * HC + lane * 4];
#pragma unroll
        for (int j = 0; j < 4; j++)
            vv[j] = *(const float4*)&g_V[(size_t)sn[j] * HC + lane * 4];

        float a[4];
#pragma unroll
        for (int j = 0; j < 4; j++) {
            float part = qv.x * kv[j].x + qv.y * kv[j].y + qv.z * kv[j].z + qv.w * kv[j].w
                       + ea[j].x * p0 + ea[j].y * p1;
            part += __shfl_xor_sync(0xffffffffu, part, 1);
            part += __shfl_xor_sync(0xffffffffu, part, 2);
            part += __shfl_xor_sync(0xffffffffu, part, 4);
            a[j] = part * 0.17677669529663687f;
        }
        float nm = fmaxf(m, fmaxf(fmaxf(a[0], a[1]), fmaxf(a[2], a[3])));
        float sc = __expf(m - nm);
        float pe0 = __expf(a[0] - nm), pe1 = __expf(a[1] - nm);
        float pe2 = __expf(a[2] - nm), pe3 = __expf(a[3] - nm);
        s = s * sc + ((pe0 + pe1) + (pe2 + pe3));
        ax = ax * sc + ((pe0 * vv[0].x + pe1 * vv[1].x) + (pe2 * vv[2].x + pe3 * vv[3].x));
        ay = ay * sc + ((pe0 * vv[0].y + pe1 * vv[1].y) + (pe2 * vv[2].y + pe3 * vv[3].y));
        az = az * sc + ((pe0 * vv[0].z + pe1 * vv[1].z) + (pe2 * vv[2].z + pe3 * vv[3].z));
        aw = aw * sc + ((pe0 * vv[0].w + pe1 * vv[1].w) + (pe2 * vv[2].w + pe3 * vv[3].w));
        g0 = g0 * sc + ((pe0 * ea[0].x + pe1 * ea[1].x) + (pe2 * ea[2].x + pe3 * ea[3].x));
        g1 = g1 * sc + ((pe0 * ea[0].y + pe1 * ea[1].y) + (pe2 * ea[2].y + pe3 * ea[3].y));
        m = nm;
    }
    for (; p < end; p++) {
        int sn = g_srcs[p];
        float2 ea2 = *(const float2*)&g_EAp[(size_t)p * EDIM + 2 * sub];
        float4 kv = *(const float4*)&g_K[(size_t)sn * HC + lane * 4];
        float part = qv.x * kv.x + qv.y * kv.y + qv.z * kv.z + qv.w * kv.w
                   + ea2.x * p0 + ea2.y * p1;
        part += __shfl_xor_sync(0xffffffffu, part, 1);
        part += __shfl_xor_sync(0xffffffffu, part, 2);
        part += __shfl_xor_sync(0xffffffffu, part, 4);
        float a = part * 0.17677669529663687f;
        float nm = fmaxf(m, a);
        float sc = __expf(m - nm);
        float pe = __expf(a - nm);
        s = s * sc + pe;
        float4 vv = *(const float4*)&g_V[(size_t)sn * HC + lane * 4];
        ax = ax * sc + pe * vv.x;
        ay = ay * sc + pe * vv.y;
        az = az * sc + pe * vv.z;
        aw = aw * sc + pe * vv.w;
        g0 = g0 * sc + pe * ea2.x;
        g1 = g1 * sc + pe * ea2.y;
        m = nm;
    }

    float ex = 0.f, ey = 0.f, ez = 0.f, ew_ = 0.f;
    int base = lane & ~7;
#pragma unroll
    for (int j = 0; j < 8; j++) {
        float gg0 = __shfl_sync(0xffffffffu, g0, base + j);
        float gg1 = __shfl_sync(0xffffffffu, g1, base + j);
        float4 w0 = ews[(2 * j) * 32 + lane];
        float4 w1 = ews[(2 * j + 1) * 32 + lane];
        ex += gg0 * w0.x + gg1 * w1.x;
        ey += gg0 * w0.y + gg1 * w1.y;
        ez += gg0 * w0.z + gg1 * w1.z;
        ew_ += gg0 * w0.w + gg1 * w1.w;
    }

    float inv = (end > beg) ? (1.f / s) : 0.f;
    size_t o = (size_t)node * HC + lane * 4;
    float4 sv = *(const float4*)&g_S[o];
    float4 y = make_float4((ax + ex) * inv + sv.x, (ay + ey) * inv + sv.y,
                           (az + ez) * inv + sv.z, (aw + ew_) * inv + sv.w);
    *(float4*)&g_S[o] = y;
}

// ---------------- batchnorm + relu ----------------
__global__ void k_bn_reduce() {
    int c = threadIdx.x;
    float sum = 0.f, sq = 0.f;
    for (int n = blockIdx.x; n < NN; n += gridDim.x) {
        float v = g_S[(size_t)n * HC + c];
        sum += v; sq += v * v;
    }
    atomicAdd(&g_bnsum[c], sum);
    atomicAdd(&g_bnsq[c], sq);
}

__global__ void k_bn_apply(const float* __restrict__ gamma,
                           const float* __restrict__ beta,
                           float* __restrict__ out, int do_split)
{
    int i = blockIdx.x * blockDim.x + threadIdx.x;
    if (i >= NN * HC) return;
    int c = i & 127;
    int n = i >> 7;
    float mean = g_bnsum[c] * (1.f / NN);
    float var = fmaf(-mean, mean, g_bnsq[c] * (1.f / NN));
    float v = (g_S[i] - mean) * rsqrtf(var + BN_EPS) * gamma[c] + beta[c];
    float r = fmaxf(v, 0.f);
    out[i] = r;
    if (do_split) {
        int s = c >> 4, r15 = c & 15;
        int t, pq;
        if (r15 < 8) { t = r15 >> 1; pq = r15 & 1; }
        else { t = (r15 - 8) >> 1; pq = 2 + (r15 & 1); }
        int pos = s * 16 + t * 4 + pq;
        unsigned short h, l;
        bf16_split(r, h, l);
        g_Ah[(size_t)n * HC + pos] = __ushort_as_bfloat16(h);
        g_Al[(size_t)n * HC + pos] = __ushort_as_bfloat16(l);
    }
}

// ---------------- driver ----------------
extern "C" void kernel_launch(void* const* d_in, const int* in_sizes, int n_in,
                              void* d_out, int out_size)
{
    const float* x  = (const float*)d_in[0];
    const int*   ei = (const int*)d_in[1];
    const float* ea = (const float*)d_in[2];
    const int* src = ei;
    const int* dst = ei + EE;

    float* out = (float*)d_out;
    float* x1 = out;
    float* x2 = out + (size_t)NN * HC;

    float *Q, *K, *V, *S;
    cudaGetSymbolAddress((void**)&Q, g_Q);
    cudaGetSymbolAddress((void**)&K, g_K);
    cudaGetSymbolAddress((void**)&V, g_V);
    cudaGetSymbolAddress((void**)&S, g_S);

    cudaFuncSetAttribute(k_gemm4, cudaFuncAttributeMaxDynamicSharedMemorySize, G4_SMEM);

    const int NB1 = (NN + 255) / 256;
    const dim3 gg4((NN + 127) / 128, 4);
    const int nthrA = NN * 32;
    const int nthrSplit = nthrA + 8 * 4096;

    for (int L = 0; L < 2; L++) {
        int b = 3 + L * 11;
        const float* qb = (const float*)d_in[b + 1];
        const float* kb = (const float*)d_in[b + 3];
        const float* vb = (const float*)d_in[b + 5];
        const float* sb = (const float*)d_in[b + 8];
        const float* bg = (const float*)d_in[b + 9];
        const float* bb = (const float*)d_in[b + 10];
        const float* ew = (const float*)d_in[b + 6];

        if (L == 0) {
            k_split<<<(nthrSplit + 255) / 256, 256>>>(
                x,
                (const float*)d_in[3], (const float*)d_in[5],
                (const float*)d_in[7], (const float*)d_in[10],
                (const float*)d_in[14], (const float*)d_in[16],
                (const float*)d_in[18], (const float*)d_in[21], nthrA);           // 0
            k_zero_csr<<<NB1, 256>>>();                                            // 1
            k_hist<<<(EE + 255) / 256, 256>>>(dst);                                // 2
            k_gemm4<<<gg4, 256, G4_SMEM>>>(qb, kb, vb, sb, Q, K, V, S, NN, 0);     // 3 (profiled)
            k_scan1<<<NB1, 256>>>();
            k_scan2<<<1, 256>>>(NB1);
            k_scan3<<<NB1, 256>>>();
            k_fillperm<<<(EE + 255) / 256, 256>>>(dst, src, ea);
        } else {
            k_gemm4<<<gg4, 256, G4_SMEM>>>(qb, kb, vb, sb, Q, K, V, S, NN, 4);
        }

        k_edge<<<(NN * 32 + 255) / 256, 256>>>(ew);

        k_bn_reduce<<<512, 128>>>();
        k_bn_apply<<<(NN * HC + 255) / 256, 256>>>(bg, bb, (L == 0) ? x1 : x2,
                                                   (L == 0) ? 1 : 0);
    }
}